// round 12
// baseline (speedup 1.0000x reference)
#include <cuda_runtime.h>
#include <math.h>

#define BB 8
#define TT 8192
#define DD 128
#define KD 64
#define NTHREADS 256

// GEMM geometry
#define GROWS 128
#define NGEMM (BB * TT / GROWS)   // 512 (+1 prep block at bid 0)

// Scan geometry
#define CL2 128
#define NCHUNK2 (TT / CL2)        // 64
#define NSCAN (BB * NCHUNK2)      // 512
#define NGROUP 4
#define GLEN (CL2 / NGROUP)       // 32

typedef unsigned long long ull;

// ---------------- device globals ----------------
__device__ float g_u[BB * TT * KD];      // 16MB scratch: raw u (unnormalized)
__device__ float g_a0[KD];
__device__ float g_w0[KD];
__device__ float g_bias[KD];
__device__ float g_invs;

__device__ float g_aggL[NSCAN * KD * 4]; // local (Zr,Zi,Ur,Ui)
__device__ int   g_flag[NSCAN];

// ---------------- math helpers ----------------
__device__ __forceinline__ float softplusf(float x) {
    return (x > 20.0f) ? x : log1pf(expf(x));
}
// z = rho * e^{i theta}; alpha*dt and theta are tiny (<~2e-3) -> Taylor (err ~1e-9)
__device__ __forceinline__ void zval2(float am, float om_, float tm, float dtv,
                                      float a0k, float w0k, float& rc, float& rs) {
    float ea = __expf(am + tm);
    float eo = __expf(om_ + tm);
    float x  = a0k * ea * dtv;
    float th = w0k * eo * dtv;
    float rho = 1.0f - x * fmaf(-0.5f, x, 1.0f);
    float th2 = th * th;
    float ct  = fmaf(-0.5f, th2, 1.0f);
    float st  = th * fmaf(-0.16666667f, th2, 1.0f);
    rc = rho * ct;
    rs = rho * st;
}
__device__ __forceinline__ ull pk2(float v) {
    ull r; asm("mov.b64 %0, {%1, %1};" : "=l"(r) : "f"(v)); return r;
}
__device__ __forceinline__ void fma2(ull& d, ull a, ull b) {
    asm("fma.rn.f32x2 %0, %1, %2, %0;" : "+l"(d) : "l"(a), "l"(b));
}
__device__ __forceinline__ void upk(ull v, float& lo, float& hi) {
    asm("mov.b64 {%0, %1}, %2;" : "=f"(lo), "=f"(hi) : "l"(v));
}

// ---------------- prep (block 0 of gemm kernel); smem need = 13312+256 floats ----------------
__device__ void do_prep(float* sm, const float* __restrict__ W,
                        const float* __restrict__ bvec,
                        const float* __restrict__ s_real,
                        const float* __restrict__ s_imag,
                        const float* __restrict__ tau_raw, int tid) {
    float* WsT = sm;                 // 128 x 68 = 8704 floats (dead after G)
    float* Am  = sm + 8704;          // 64 x 68 = 4352
    float* Bm  = sm;                 // overlays WsT
    float* pv  = sm + 8704 + 4352;   // 64
    float* py  = pv + 64;            // 128
    float* pred = py + 128;          // 64

    // reset scan lookback flags (512)
    g_flag[tid] = 0;
    g_flag[tid + 256] = 0;

    // load W transposed: WsT[d][k]
    for (int i = tid; i < 64 * 32; i += NTHREADS) {
        int k = i >> 5, q = i & 31;
        float4 w4 = *(const float4*)&W[k * DD + q * 4];
        WsT[(q * 4 + 0) * 68 + k] = w4.x;
        WsT[(q * 4 + 1) * 68 + k] = w4.y;
        WsT[(q * 4 + 2) * 68 + k] = w4.z;
        WsT[(q * 4 + 3) * 68 + k] = w4.w;
    }
    __syncthreads();

    const int i0 = (tid >> 4) * 4;
    const int j0 = (tid & 15) * 4;

    {   // G = W W^T -> Am
        ull acc2[4][2];
#pragma unroll
        for (int a = 0; a < 4; a++) { acc2[a][0] = 0ull; acc2[a][1] = 0ull; }
        for (int d = 0; d < DD; d++) {
            float4 si = *(const float4*)&WsT[d * 68 + i0];
            ull sj0 = *(const ull*)&WsT[d * 68 + j0];
            ull sj1 = *(const ull*)&WsT[d * 68 + j0 + 2];
            ull xx;
            xx = pk2(si.x); fma2(acc2[0][0], xx, sj0); fma2(acc2[0][1], xx, sj1);
            xx = pk2(si.y); fma2(acc2[1][0], xx, sj0); fma2(acc2[1][1], xx, sj1);
            xx = pk2(si.z); fma2(acc2[2][0], xx, sj0); fma2(acc2[2][1], xx, sj1);
            xx = pk2(si.w); fma2(acc2[3][0], xx, sj0); fma2(acc2[3][1], xx, sj1);
        }
        __syncthreads();   // all reads of WsT done before Bm (=WsT) is written in sq1
#pragma unroll
        for (int a = 0; a < 4; a++) {
            float lo, hi;
            upk(acc2[a][0], lo, hi);
            Am[(i0 + a) * 68 + j0 + 0] = lo; Am[(i0 + a) * 68 + j0 + 1] = hi;
            upk(acc2[a][1], lo, hi);
            Am[(i0 + a) * 68 + j0 + 2] = lo; Am[(i0 + a) * 68 + j0 + 3] = hi;
        }
    }
    __syncthreads();

    // 4 squarings: Am holds G; after sq4, Am = G^16 (lambda^16 ~ 2e7, fits fp32)
    const float* srcs[4] = {Am, Bm, Am, Bm};
    float* dsts[4] = {Bm, Am, Bm, Am};
    for (int sq = 0; sq < 4; sq++) {
        const float* src = srcs[sq];
        float* dst = dsts[sq];
        ull acc2[4][2];
#pragma unroll
        for (int a = 0; a < 4; a++) { acc2[a][0] = 0ull; acc2[a][1] = 0ull; }
        for (int l = 0; l < 64; l++) {
            float4 si = *(const float4*)&src[l * 68 + i0];
            ull sj0 = *(const ull*)&src[l * 68 + j0];
            ull sj1 = *(const ull*)&src[l * 68 + j0 + 2];
            ull xx;
            xx = pk2(si.x); fma2(acc2[0][0], xx, sj0); fma2(acc2[0][1], xx, sj1);
            xx = pk2(si.y); fma2(acc2[1][0], xx, sj0); fma2(acc2[1][1], xx, sj1);
            xx = pk2(si.z); fma2(acc2[2][0], xx, sj0); fma2(acc2[2][1], xx, sj1);
            xx = pk2(si.w); fma2(acc2[3][0], xx, sj0); fma2(acc2[3][1], xx, sj1);
        }
        __syncthreads();
#pragma unroll
        for (int a = 0; a < 4; a++) {
            float lo, hi;
            upk(acc2[a][0], lo, hi);
            dst[(i0 + a) * 68 + j0 + 0] = lo; dst[(i0 + a) * 68 + j0 + 1] = hi;
            upk(acc2[a][1], lo, hi);
            dst[(i0 + a) * 68 + j0 + 2] = lo; dst[(i0 + a) * 68 + j0 + 3] = hi;
        }
        __syncthreads();
    }

    if (tid < 64) pv[tid] = 1.0f + 0.001f * (float)tid;
    __syncthreads();

    // 8 power iterations on Am = G^16
    for (int it = 0; it < 8; it++) {
        if (tid < 64) {
            float s = 0.0f;
#pragma unroll 4
            for (int j = 0; j < 64; j += 4) {
                float4 m4 = *(const float4*)&Am[tid * 68 + j];
                float4 v4 = *(const float4*)&pv[j];
                s = fmaf(m4.x, v4.x, s); s = fmaf(m4.y, v4.y, s);
                s = fmaf(m4.z, v4.z, s); s = fmaf(m4.w, v4.w, s);
            }
            py[tid] = s;
            pred[tid] = s * s;
        }
        __syncthreads();
        for (int s = 32; s > 0; s >>= 1) {
            if (tid < s) pred[tid] += pred[tid + s];
            __syncthreads();
        }
        if (tid < 64) pv[tid] = py[tid] * rsqrtf(pred[0]);
        __syncthreads();
    }

    // sigma^2 = ||W^T v||^2 (v = unit top eigvec)
    if (tid < 128) {
        float s = 0.0f;
#pragma unroll 4
        for (int k = 0; k < 64; k++) s = fmaf(W[k * DD + tid], pv[k], s);
        py[tid] = s * s;
    }
    __syncthreads();
    if (tid < 64) pred[tid] = py[tid] + py[tid + 64];
    __syncthreads();
    for (int s = 32; s > 0; s >>= 1) {
        if (tid < s) pred[tid] += pred[tid + s];
        __syncthreads();
    }
    if (tid == 0) g_invs = rsqrtf(pred[0]);
    if (tid < 64) {
        float tau = softplusf(tau_raw[0]) + 1e-3f;
        g_a0[tid] = (softplusf(s_real[tid]) + 1e-6f) * tau;
        g_w0[tid] = s_imag[tid] * tau;
        g_bias[tid] = bvec[tid];
    }
}

// ---------------- kernel A: FFMA2 GEMM (4t x 8k tiles, 3 CTAs/SM) + prep block 0 ----------------
__global__ void __launch_bounds__(NTHREADS, 3)
gemm_kernel(const float* __restrict__ x, const float* __restrict__ W,
            const float* __restrict__ bvec, const float* __restrict__ s_real,
            const float* __restrict__ s_imag, const float* __restrict__ tau_raw) {
    extern __shared__ float sm[];
    const int bid = blockIdx.x;
    const int tid = threadIdx.x;

    if (bid == 0) {                 // prep block, scheduled first
        do_prep(sm, W, bvec, s_real, s_imag, tau_raw, tid);
        return;
    }
    const int gb = bid - 1;

    float* xs = sm;                 // 128 x 36 = 4608 floats
    float* wc = sm + 4608;          // 32 x 64  = 2048 floats

    const int ty = tid >> 3;        // 0..31 : 4 rows each
    const int tx = tid & 7;         // 0..7  : 8 k cols each

    ull acc[4][4];
#pragma unroll
    for (int i = 0; i < 4; i++)
#pragma unroll
        for (int p = 0; p < 4; p++) acc[i][p] = 0ull;

    const float* xg = x + (size_t)gb * GROWS * DD;
    const int kk = tid & 63;
    const int qq = tid >> 6;        // 0..3

#pragma unroll 1
    for (int dc = 0; dc < 4; dc++) {     // d chunks of 32
        __syncthreads();
        // stage x chunk: 128 rows x 32 d
#pragma unroll
        for (int j = 0; j < 4; j++) {
            int f = tid + j * NTHREADS;
            int row = f >> 3, q = f & 7;
            *(float4*)&xs[row * 36 + q * 4] =
                *(const float4*)&xg[(size_t)row * DD + dc * 32 + q * 4];
        }
        // stage W chunk transposed: wc[d][k]
        {
            const float* wp = &W[kk * DD + dc * 32 + qq * 8];
            float4 a = *(const float4*)wp;
            float4 b = *(const float4*)(wp + 4);
            wc[(qq * 8 + 0) * 64 + kk] = a.x;
            wc[(qq * 8 + 1) * 64 + kk] = a.y;
            wc[(qq * 8 + 2) * 64 + kk] = a.z;
            wc[(qq * 8 + 3) * 64 + kk] = a.w;
            wc[(qq * 8 + 4) * 64 + kk] = b.x;
            wc[(qq * 8 + 5) * 64 + kk] = b.y;
            wc[(qq * 8 + 6) * 64 + kk] = b.z;
            wc[(qq * 8 + 7) * 64 + kk] = b.w;
        }
        __syncthreads();

#pragma unroll
        for (int d2 = 0; d2 < 16; d2++) {     // 2 d per step
            ull w0[4], w1[4];
            const ull* p0 = (const ull*)&wc[(2 * d2) * 64 + tx * 8];
            const ull* p1 = (const ull*)&wc[(2 * d2 + 1) * 64 + tx * 8];
#pragma unroll
            for (int p = 0; p < 4; p++) { w0[p] = p0[p]; w1[p] = p1[p]; }
#pragma unroll
            for (int i = 0; i < 4; i++) {
                float2 xv = *(const float2*)&xs[(ty * 4 + i) * 36 + 2 * d2];
                ull x0 = pk2(xv.x);
#pragma unroll
                for (int p = 0; p < 4; p++) fma2(acc[i][p], x0, w0[p]);
                ull x1 = pk2(xv.y);
#pragma unroll
                for (int p = 0; p < 4; p++) fma2(acc[i][p], x1, w1[p]);
            }
        }
    }

    // epilogue: write raw u
#pragma unroll
    for (int i = 0; i < 4; i++) {
        ull* up = (ull*)&g_u[((size_t)gb * GROWS + ty * 4 + i) * KD + tx * 8];
#pragma unroll
        for (int p = 0; p < 4; p++) up[p] = acc[i][p];
    }
}

// ---------------- kernel B: scan (compose + windowed lookback + replay) ----------------
__global__ void __launch_bounds__(NTHREADS, 4)
scan_kernel(const float* __restrict__ dtv_g, const float* __restrict__ amod,
            const float* __restrict__ omod, const float* __restrict__ tmod,
            float* __restrict__ out) {
    __shared__ float agg[NGROUP * KD * 4];
    __shared__ float pre[NGROUP * KD * 4];
    __shared__ float carry[2 * KD];

    const int bid   = blockIdx.x;
    const int b     = bid % BB;
    const int chunk = bid / BB;
    const int tid   = threadIdx.x;
    const int t0    = chunk * CL2;
    const int fidx  = b * NCHUNK2 + chunk;

    const int k = tid & 63;
    const int g = tid >> 6;
    const float a0k = g_a0[k];
    const float w0k = g_w0[k];
    const float invs = g_invs;
    const float bk = g_bias[k];

    const size_t base_bt = (size_t)b * TT + t0 + g * GLEN;
    const float* amp = amod + base_bt * KD + k;
    const float* omp_ = omod + base_bt * KD + k;
    const float* tmp_ = tmod + base_bt;
    const float* dtp = dtv_g + base_bt;
    const float* up_ = g_u + base_bt * KD + k;

    // ---------- compose (carry-free) ----------
    float Zr = 1.0f, Zi = 0.0f, Ur = 0.0f, Ui = 0.0f;
#pragma unroll 4
    for (int i = 0; i < GLEN; i++) {
        float rc, rs;
        zval2(amp[(size_t)i * KD], omp_[(size_t)i * KD], tmp_[i], dtp[i], a0k, w0k, rc, rs);
        float u = fmaf(up_[(size_t)i * KD], invs, bk);
        float Ur2 = fmaf(rc, Ur, fmaf(-rs, Ui, u));
        float Ui2 = fmaf(rc, Ui, rs * Ur);
        float Zr2 = fmaf(rc, Zr, -rs * Zi);
        float Zi2 = fmaf(rc, Zi, rs * Zr);
        Ur = Ur2; Ui = Ui2; Zr = Zr2; Zi = Zi2;
    }
    {
        float* a = &agg[(g * 64 + k) * 4];
        a[0] = Zr; a[1] = Zi; a[2] = Ur; a[3] = Ui;
    }
    __syncthreads();

    // ---------- intra-block group scan + publish local aggregate ----------
    if (tid < 64) {
        float zr = 1.0f, zi = 0.0f, ur = 0.0f, ui = 0.0f;
#pragma unroll
        for (int gg = 0; gg < NGROUP; gg++) {
            float* p = &pre[(gg * 64 + k) * 4];
            p[0] = zr; p[1] = zi; p[2] = ur; p[3] = ui;
            float* a = &agg[(gg * 64 + k) * 4];
            float azr = a[0], azi = a[1], aur = a[2], aui = a[3];
            float nzr = azr * zr - azi * zi;
            float nzi = azr * zi + azi * zr;
            float nur = fmaf(azr, ur, fmaf(-azi, ui, aur));
            float nui = fmaf(azr, ui, fmaf(azi, ur, aui));
            zr = nzr; zi = nzi; ur = nur; ui = nui;
        }
        float* Lb = &g_aggL[((size_t)fidx * KD + k) * 4];
        Lb[0] = zr; Lb[1] = zi; Lb[2] = ur; Lb[3] = ui;
    }
    __syncthreads();
    if (tid == 0) {
        __threadfence();
        atomicExch(&g_flag[fidx], 1);
    }

    // ---------- windowed parallel lookback (4 predecessors per step) ----------
    {
        const int kq = tid >> 2;      // k handled by this 4-lane group
        const int g4 = tid & 3;       // window lane (0 = newest)
        float czr = 1.0f, czi = 0.0f, cur = 0.0f, cui = 0.0f;
        for (int base = chunk - 1; base >= 0; base -= 4) {
            int p = base - g4;
            float wzr = 1.0f, wzi = 0.0f, wur = 0.0f, wui = 0.0f;
            if (p >= 0) {
                volatile int* vf = (volatile int*)&g_flag[b * NCHUNK2 + p];
                while (*vf == 0) { }
                __threadfence();
                float4 a4 = __ldcg((const float4*)&g_aggL[(((size_t)b * NCHUNK2 + p) * KD + kq) * 4]);
                wzr = a4.x; wzi = a4.y; wur = a4.z; wui = a4.w;
            }
            // ordered tree combine within 4 lanes: W = newest∘...∘oldest
#pragma unroll
            for (int st = 1; st <= 2; st <<= 1) {
                float ozr = __shfl_xor_sync(0xffffffff, wzr, st);
                float ozi = __shfl_xor_sync(0xffffffff, wzi, st);
                float our = __shfl_xor_sync(0xffffffff, wur, st);
                float oui = __shfl_xor_sync(0xffffffff, wui, st);
                bool newer = ((g4 & st) == 0);
                float fzr = newer ? wzr : ozr, fzi = newer ? wzi : ozi;
                float fur = newer ? wur : our, fui = newer ? wui : oui;
                float gzr = newer ? ozr : wzr, gzi = newer ? ozi : wzi;
                float gur = newer ? our : wur, gui = newer ? oui : wui;
                wzr = fzr * gzr - fzi * gzi;
                wzi = fzr * gzi + fzi * gzr;
                wur = fmaf(fzr, gur, fmaf(-fzi, gui, fur));
                wui = fmaf(fzr, gui, fmaf(fzi, gur, fui));
            }
            // c := c ∘ W (window is older than accumulated part)
            float nzr = czr * wzr - czi * wzi;
            float nzi = czr * wzi + czi * wzr;
            float nur = fmaf(czr, wur, fmaf(-czi, wui, cur));
            float nui = fmaf(czr, wui, fmaf(czi, wur, cui));
            czr = nzr; czi = nzi; cur = nur; cui = nui;
        }
        if (g4 == 0) {
            carry[kq] = cur;
            carry[64 + kq] = cui;
        }
    }
    __syncthreads();

    // ---------- replay with carry, write output ----------
    float pzr = pre[(g * 64 + k) * 4 + 0];
    float pzi = pre[(g * 64 + k) * 4 + 1];
    float pur = pre[(g * 64 + k) * 4 + 2];
    float pui = pre[(g * 64 + k) * 4 + 3];
    float chr_ = carry[k];
    float chi  = carry[64 + k];
    float hr = fmaf(pzr, chr_, fmaf(-pzi, chi, pur));
    float hi = fmaf(pzr, chi, fmaf(pzi, chr_, pui));

    float* outp = out + base_bt * (2 * KD);
#pragma unroll 4
    for (int i = 0; i < GLEN; i++) {
        float rc, rs;
        zval2(amp[(size_t)i * KD], omp_[(size_t)i * KD], tmp_[i], dtp[i], a0k, w0k, rc, rs);
        float u = fmaf(up_[(size_t)i * KD], invs, bk);
        float hr2 = fmaf(rc, hr, fmaf(-rs, hi, u));
        float hi2 = fmaf(rc, hi, rs * hr);
        hr = hr2; hi = hi2;
        outp[(size_t)i * 128 + k]      = hr;
        outp[(size_t)i * 128 + 64 + k] = hi;
    }
}

// ---------------- launch ----------------
extern "C" void kernel_launch(void* const* d_in, const int* in_sizes, int n_in,
                              void* d_out, int out_size) {
    const float* x      = (const float*)d_in[0];
    const float* dt     = (const float*)d_in[1];
    const float* amod   = (const float*)d_in[2];
    const float* omod   = (const float*)d_in[3];
    const float* tmod   = (const float*)d_in[4];
    const float* s_real = (const float*)d_in[5];
    const float* s_imag = (const float*)d_in[6];
    const float* tau_r  = (const float*)d_in[7];
    const float* W      = (const float*)d_in[8];
    const float* bvec   = (const float*)d_in[9];
    float* out = (float*)d_out;

    // dynamic smem = max(prep 13568 floats, gemm 6656 floats)
    static const size_t smem = (size_t)(8704 + 4352 + 64 + 128 + 64) * sizeof(float); // 53.2KB

    cudaFuncSetAttribute(gemm_kernel, cudaFuncAttributeMaxDynamicSharedMemorySize, (int)smem);

    gemm_kernel<<<NGEMM + 1, NTHREADS, smem>>>(x, W, bvec, s_real, s_imag, tau_r);
    scan_kernel<<<NSCAN, NTHREADS>>>(dt, amod, omod, tmod, out);
}

// round 14
// speedup vs baseline: 1.0438x; 1.0438x over previous
#include <cuda_runtime.h>
#include <math.h>

#define BB 8
#define TT 8192
#define DD 128
#define KD 64
#define NTHREADS 256

#define GROWS 128
#define NGEMMB 512                 // gemm blocks (bid 1..512)

#define CL2 128
#define NCHUNK2 (TT / CL2)         // 64
#define NSCAN 512                  // scan blocks (bid 513..1024)
#define NGROUP 4
#define GLEN (CL2 / NGROUP)        // 32

#define NBLK_TOTAL (1 + NGEMMB + NSCAN)   // 1025

typedef unsigned long long ull;

// ---------------- device globals ----------------
__device__ float g_u[BB * TT * KD];      // 16MB scratch: raw u (unnormalized)
__device__ float g_a0[KD];
__device__ float g_w0[KD];
__device__ float g_bias[KD];
__device__ float g_invs;

__device__ float g_aggL[NSCAN * KD * 4]; // local (Zr,Zi,Ur,Ui)
__device__ int   g_flag[NSCAN];          // scan lookback flags
__device__ int   g_uflag[NGEMMB];        // gemm->scan ready flags
__device__ int   g_ready;                // prep done
__device__ int   g_done;                 // cleanup counter

// ---------------- math helpers ----------------
__device__ __forceinline__ float softplusf(float x) {
    return (x > 20.0f) ? x : log1pf(expf(x));
}
// z = rho * e^{i theta}; alpha*dt and theta are tiny (<~2e-3) -> Taylor (err ~1e-9)
__device__ __forceinline__ void zval2(float am, float om_, float tm, float dtv,
                                      float a0k, float w0k, float& rc, float& rs) {
    float ea = __expf(am + tm);
    float eo = __expf(om_ + tm);
    float x  = a0k * ea * dtv;
    float th = w0k * eo * dtv;
    float rho = 1.0f - x * fmaf(-0.5f, x, 1.0f);
    float th2 = th * th;
    float ct  = fmaf(-0.5f, th2, 1.0f);
    float st  = th * fmaf(-0.16666667f, th2, 1.0f);
    rc = rho * ct;
    rs = rho * st;
}
__device__ __forceinline__ ull pk2(float v) {
    ull r; asm("mov.b64 %0, {%1, %1};" : "=l"(r) : "f"(v)); return r;
}
__device__ __forceinline__ void fma2(ull& d, ull a, ull b) {
    asm("fma.rn.f32x2 %0, %1, %2, %0;" : "+l"(d) : "l"(a), "l"(b));
}
__device__ __forceinline__ void upk(ull v, float& lo, float& hi) {
    asm("mov.b64 {%0, %1}, %2;" : "=f"(lo), "=f"(hi) : "l"(v));
}

// ---------------- prep (block 0) ----------------
__device__ void do_prep(float* sm, const float* __restrict__ W,
                        const float* __restrict__ bvec,
                        const float* __restrict__ s_real,
                        const float* __restrict__ s_imag,
                        const float* __restrict__ tau_raw, int tid) {
    float* WsT = sm;                 // 128 x 68 = 8704 floats (dead after G)
    float* Am  = sm + 8704;          // 64 x 68 = 4352
    float* Bm  = sm;                 // overlays WsT
    float* pv  = sm + 8704 + 4352;   // 64
    float* py  = pv + 64;            // 128
    float* pred = py + 128;          // 64

    // load W transposed: WsT[d][k]
    for (int i = tid; i < 64 * 32; i += NTHREADS) {
        int k = i >> 5, q = i & 31;
        float4 w4 = *(const float4*)&W[k * DD + q * 4];
        WsT[(q * 4 + 0) * 68 + k] = w4.x;
        WsT[(q * 4 + 1) * 68 + k] = w4.y;
        WsT[(q * 4 + 2) * 68 + k] = w4.z;
        WsT[(q * 4 + 3) * 68 + k] = w4.w;
    }
    __syncthreads();

    const int i0 = (tid >> 4) * 4;
    const int j0 = (tid & 15) * 4;

    {   // G = W W^T -> Am
        ull acc2[4][2];
#pragma unroll
        for (int a = 0; a < 4; a++) { acc2[a][0] = 0ull; acc2[a][1] = 0ull; }
        for (int d = 0; d < DD; d++) {
            float4 si = *(const float4*)&WsT[d * 68 + i0];
            ull sj0 = *(const ull*)&WsT[d * 68 + j0];
            ull sj1 = *(const ull*)&WsT[d * 68 + j0 + 2];
            ull xx;
            xx = pk2(si.x); fma2(acc2[0][0], xx, sj0); fma2(acc2[0][1], xx, sj1);
            xx = pk2(si.y); fma2(acc2[1][0], xx, sj0); fma2(acc2[1][1], xx, sj1);
            xx = pk2(si.z); fma2(acc2[2][0], xx, sj0); fma2(acc2[2][1], xx, sj1);
            xx = pk2(si.w); fma2(acc2[3][0], xx, sj0); fma2(acc2[3][1], xx, sj1);
        }
        __syncthreads();
#pragma unroll
        for (int a = 0; a < 4; a++) {
            float lo, hi;
            upk(acc2[a][0], lo, hi);
            Am[(i0 + a) * 68 + j0 + 0] = lo; Am[(i0 + a) * 68 + j0 + 1] = hi;
            upk(acc2[a][1], lo, hi);
            Am[(i0 + a) * 68 + j0 + 2] = lo; Am[(i0 + a) * 68 + j0 + 3] = hi;
        }
    }
    __syncthreads();

    // 4 squarings: after sq4, Am = G^16 (lambda^16 ~ 2e7, fits fp32)
    const float* srcs[4] = {Am, Bm, Am, Bm};
    float* dsts[4] = {Bm, Am, Bm, Am};
    for (int sq = 0; sq < 4; sq++) {
        const float* src = srcs[sq];
        float* dst = dsts[sq];
        ull acc2[4][2];
#pragma unroll
        for (int a = 0; a < 4; a++) { acc2[a][0] = 0ull; acc2[a][1] = 0ull; }
        for (int l = 0; l < 64; l++) {
            float4 si = *(const float4*)&src[l * 68 + i0];
            ull sj0 = *(const ull*)&src[l * 68 + j0];
            ull sj1 = *(const ull*)&src[l * 68 + j0 + 2];
            ull xx;
            xx = pk2(si.x); fma2(acc2[0][0], xx, sj0); fma2(acc2[0][1], xx, sj1);
            xx = pk2(si.y); fma2(acc2[1][0], xx, sj0); fma2(acc2[1][1], xx, sj1);
            xx = pk2(si.z); fma2(acc2[2][0], xx, sj0); fma2(acc2[2][1], xx, sj1);
            xx = pk2(si.w); fma2(acc2[3][0], xx, sj0); fma2(acc2[3][1], xx, sj1);
        }
        __syncthreads();
#pragma unroll
        for (int a = 0; a < 4; a++) {
            float lo, hi;
            upk(acc2[a][0], lo, hi);
            dst[(i0 + a) * 68 + j0 + 0] = lo; dst[(i0 + a) * 68 + j0 + 1] = hi;
            upk(acc2[a][1], lo, hi);
            dst[(i0 + a) * 68 + j0 + 2] = lo; dst[(i0 + a) * 68 + j0 + 3] = hi;
        }
        __syncthreads();
    }

    if (tid < 64) pv[tid] = 1.0f + 0.001f * (float)tid;
    __syncthreads();

    for (int it = 0; it < 8; it++) {   // power iteration on G^16
        if (tid < 64) {
            float s = 0.0f;
#pragma unroll 4
            for (int j = 0; j < 64; j += 4) {
                float4 m4 = *(const float4*)&Am[tid * 68 + j];
                float4 v4 = *(const float4*)&pv[j];
                s = fmaf(m4.x, v4.x, s); s = fmaf(m4.y, v4.y, s);
                s = fmaf(m4.z, v4.z, s); s = fmaf(m4.w, v4.w, s);
            }
            py[tid] = s;
            pred[tid] = s * s;
        }
        __syncthreads();
        for (int s = 32; s > 0; s >>= 1) {
            if (tid < s) pred[tid] += pred[tid + s];
            __syncthreads();
        }
        if (tid < 64) pv[tid] = py[tid] * rsqrtf(pred[0]);
        __syncthreads();
    }

    // sigma^2 = ||W^T v||^2
    if (tid < 128) {
        float s = 0.0f;
#pragma unroll 4
        for (int k = 0; k < 64; k++) s = fmaf(W[k * DD + tid], pv[k], s);
        py[tid] = s * s;
    }
    __syncthreads();
    if (tid < 64) pred[tid] = py[tid] + py[tid + 64];
    __syncthreads();
    for (int s = 32; s > 0; s >>= 1) {
        if (tid < s) pred[tid] += pred[tid + s];
        __syncthreads();
    }
    if (tid == 0) g_invs = rsqrtf(pred[0]);
    if (tid < 64) {
        float tau = softplusf(tau_raw[0]) + 1e-3f;
        g_a0[tid] = (softplusf(s_real[tid]) + 1e-6f) * tau;
        g_w0[tid] = s_imag[tid] * tau;
        g_bias[tid] = bvec[tid];
    }
    __syncthreads();
    if (tid == 0) {
        __threadfence();
        atomicExch(&g_ready, 1);
    }
}

// ---------------- gemm part (bid 1..512) ----------------
__device__ void do_gemm(float* sm, const float* __restrict__ x,
                        const float* __restrict__ W, int gb, int tid) {
    float* Wt = sm;             // 128 x 68 = 8704 floats
    float* xs = sm + 8704;      // 128 x 36 = 4608 floats

    // stage W^T once: Wt[d][k]
    for (int i = tid; i < 64 * 32; i += NTHREADS) {
        int k = i >> 5, q = i & 31;
        float4 w4 = *(const float4*)&W[k * DD + q * 4];
        Wt[(q * 4 + 0) * 68 + k] = w4.x;
        Wt[(q * 4 + 1) * 68 + k] = w4.y;
        Wt[(q * 4 + 2) * 68 + k] = w4.z;
        Wt[(q * 4 + 3) * 68 + k] = w4.w;
    }

    const int ty = tid >> 3;    // 0..31 : 4 rows each
    const int tx = tid & 7;     // 0..7  : 8 k cols each

    ull acc[4][4];
#pragma unroll
    for (int i = 0; i < 4; i++)
#pragma unroll
        for (int p = 0; p < 4; p++) acc[i][p] = 0ull;

    const float* xg = x + (size_t)gb * GROWS * DD;

#pragma unroll 1
    for (int dc = 0; dc < 4; dc++) {
        if (dc) __syncthreads();
        // stage x chunk: 128 rows x 32 d
#pragma unroll
        for (int j = 0; j < 4; j++) {
            int f = tid + j * NTHREADS;
            int row = f >> 3, q = f & 7;
            *(float4*)&xs[row * 36 + q * 4] =
                *(const float4*)&xg[(size_t)row * DD + dc * 32 + q * 4];
        }
        __syncthreads();

#pragma unroll
        for (int d2 = 0; d2 < 16; d2++) {
            int d = dc * 32 + d2 * 2;
            ulonglong2 wA = *(const ulonglong2*)&Wt[d * 68 + tx * 8];
            ulonglong2 wB = *(const ulonglong2*)&Wt[d * 68 + tx * 8 + 4];
            ulonglong2 wC = *(const ulonglong2*)&Wt[(d + 1) * 68 + tx * 8];
            ulonglong2 wD = *(const ulonglong2*)&Wt[(d + 1) * 68 + tx * 8 + 4];
#pragma unroll
            for (int i = 0; i < 4; i++) {
                float2 xv = *(const float2*)&xs[(ty * 4 + i) * 36 + d2 * 2];
                ull x0 = pk2(xv.x);
                fma2(acc[i][0], x0, wA.x); fma2(acc[i][1], x0, wA.y);
                fma2(acc[i][2], x0, wB.x); fma2(acc[i][3], x0, wB.y);
                ull x1 = pk2(xv.y);
                fma2(acc[i][0], x1, wC.x); fma2(acc[i][1], x1, wC.y);
                fma2(acc[i][2], x1, wD.x); fma2(acc[i][3], x1, wD.y);
            }
        }
    }

    // epilogue: write raw u (STG.128)
#pragma unroll
    for (int i = 0; i < 4; i++) {
        ull* up = (ull*)&g_u[((size_t)gb * GROWS + ty * 4 + i) * KD + tx * 8];
        ulonglong2 v0; v0.x = acc[i][0]; v0.y = acc[i][1];
        ulonglong2 v1; v1.x = acc[i][2]; v1.y = acc[i][3];
        *(ulonglong2*)&up[0] = v0;
        *(ulonglong2*)&up[2] = v1;
    }
    __syncthreads();
    if (tid == 0) {
        __threadfence();
        atomicExch(&g_uflag[gb], 1);
    }
}

// ---------------- scan part (bid 513..1024) ----------------
__device__ void do_scan(float* sm, const float* __restrict__ dtv_g,
                        const float* __restrict__ amod, const float* __restrict__ omod,
                        const float* __restrict__ tmod, float* __restrict__ out,
                        int sid, int tid) {
    float* us    = sm;                  // 128 x 64 = 8192 floats
    float* agg   = sm + 8192;           // 1024
    float* pre   = agg + NGROUP * KD * 4;   // 1024
    float* carry = pre + NGROUP * KD * 4;   // 128

    const int b     = sid % BB;
    const int chunk = sid / BB;
    const int t0    = chunk * CL2;
    const int fidx  = b * NCHUNK2 + chunk;

    // wait for prep + our gemm block
    if (tid == 0) {
        volatile int* rp = &g_ready;
        while (*rp == 0) { }
        volatile int* uf = &g_uflag[b * NCHUNK2 + chunk];
        while (*uf == 0) { }
        __threadfence();
    }
    __syncthreads();

    const int k = tid & 63;
    const int g = tid >> 6;
    const float a0k = g_a0[k];
    const float w0k = g_w0[k];
    const float invs = g_invs;
    const float bk = g_bias[k];

    const size_t base_bt = (size_t)b * TT + t0 + g * GLEN;
    const float* amp = amod + base_bt * KD + k;
    const float* omp_ = omod + base_bt * KD + k;
    const float* tmp_ = tmod + base_bt;
    const float* dtp = dtv_g + base_bt;
    const float* up_ = g_u + base_bt * KD + k;

    // ---------- compose (carry-free) + cache u in smem ----------
    float Zr = 1.0f, Zi = 0.0f, Ur = 0.0f, Ui = 0.0f;
#pragma unroll 4
    for (int i = 0; i < GLEN; i++) {
        float rc, rs;
        zval2(amp[(size_t)i * KD], omp_[(size_t)i * KD], tmp_[i], dtp[i], a0k, w0k, rc, rs);
        float u = fmaf(__ldcg(&up_[(size_t)i * KD]), invs, bk);
        us[(g * GLEN + i) * KD + k] = u;
        float Ur2 = fmaf(rc, Ur, fmaf(-rs, Ui, u));
        float Ui2 = fmaf(rc, Ui, rs * Ur);
        float Zr2 = fmaf(rc, Zr, -rs * Zi);
        float Zi2 = fmaf(rc, Zi, rs * Zr);
        Ur = Ur2; Ui = Ui2; Zr = Zr2; Zi = Zi2;
    }
    {
        float* a = &agg[(g * 64 + k) * 4];
        a[0] = Zr; a[1] = Zi; a[2] = Ur; a[3] = Ui;
    }
    __syncthreads();

    // ---------- intra-block group scan + publish local aggregate ----------
    if (tid < 64) {
        float zr = 1.0f, zi = 0.0f, ur = 0.0f, ui = 0.0f;
#pragma unroll
        for (int gg = 0; gg < NGROUP; gg++) {
            float* p = &pre[(gg * 64 + k) * 4];
            p[0] = zr; p[1] = zi; p[2] = ur; p[3] = ui;
            float* a = &agg[(gg * 64 + k) * 4];
            float azr = a[0], azi = a[1], aur = a[2], aui = a[3];
            float nzr = azr * zr - azi * zi;
            float nzi = azr * zi + azi * zr;
            float nur = fmaf(azr, ur, fmaf(-azi, ui, aur));
            float nui = fmaf(azr, ui, fmaf(azi, ur, aui));
            zr = nzr; zi = nzi; ur = nur; ui = nui;
        }
        float* Lb = &g_aggL[((size_t)fidx * KD + k) * 4];
        Lb[0] = zr; Lb[1] = zi; Lb[2] = ur; Lb[3] = ui;
    }
    __syncthreads();
    if (tid == 0) {
        __threadfence();
        atomicExch(&g_flag[fidx], 1);
    }

    // ---------- windowed parallel lookback (4 predecessors per step) ----------
    {
        const int kq = tid >> 2;
        const int g4 = tid & 3;
        float czr = 1.0f, czi = 0.0f, cur = 0.0f, cui = 0.0f;
        for (int base = chunk - 1; base >= 0; base -= 4) {
            int p = base - g4;
            float wzr = 1.0f, wzi = 0.0f, wur = 0.0f, wui = 0.0f;
            if (p >= 0) {
                volatile int* vf = (volatile int*)&g_flag[b * NCHUNK2 + p];
                while (*vf == 0) { }
                __threadfence();
                float4 a4 = __ldcg((const float4*)&g_aggL[(((size_t)b * NCHUNK2 + p) * KD + kq) * 4]);
                wzr = a4.x; wzi = a4.y; wur = a4.z; wui = a4.w;
            }
#pragma unroll
            for (int st = 1; st <= 2; st <<= 1) {
                float ozr = __shfl_xor_sync(0xffffffff, wzr, st);
                float ozi = __shfl_xor_sync(0xffffffff, wzi, st);
                float our = __shfl_xor_sync(0xffffffff, wur, st);
                float oui = __shfl_xor_sync(0xffffffff, wui, st);
                bool newer = ((g4 & st) == 0);
                float fzr = newer ? wzr : ozr, fzi = newer ? wzi : ozi;
                float fur = newer ? wur : our, fui = newer ? wui : oui;
                float gzr = newer ? ozr : wzr, gzi = newer ? ozi : wzi;
                float gur = newer ? our : wur, gui = newer ? oui : wui;
                wzr = fzr * gzr - fzi * gzi;
                wzi = fzr * gzi + fzi * gzr;
                wur = fmaf(fzr, gur, fmaf(-fzi, gui, fur));
                wui = fmaf(fzr, gui, fmaf(fzi, gur, fui));
            }
            float nzr = czr * wzr - czi * wzi;
            float nzi = czr * wzi + czi * wzr;
            float nur = fmaf(czr, wur, fmaf(-czi, wui, cur));
            float nui = fmaf(czr, wui, fmaf(czi, wur, cui));
            czr = nzr; czi = nzi; cur = nur; cui = nui;
        }
        if (g4 == 0) {
            carry[kq] = cur;
            carry[64 + kq] = cui;
        }
    }
    __syncthreads();

    // ---------- replay with carry (u from smem), write output ----------
    float pzr = pre[(g * 64 + k) * 4 + 0];
    float pzi = pre[(g * 64 + k) * 4 + 1];
    float pur = pre[(g * 64 + k) * 4 + 2];
    float pui = pre[(g * 64 + k) * 4 + 3];
    float chr_ = carry[k];
    float chi  = carry[64 + k];
    float hr = fmaf(pzr, chr_, fmaf(-pzi, chi, pur));
    float hi = fmaf(pzr, chi, fmaf(pzi, chr_, pui));

    float* outp = out + base_bt * (2 * KD);
#pragma unroll 4
    for (int i = 0; i < GLEN; i++) {
        float rc, rs;
        zval2(amp[(size_t)i * KD], omp_[(size_t)i * KD], tmp_[i], dtp[i], a0k, w0k, rc, rs);
        float u = us[(g * GLEN + i) * KD + k];
        float hr2 = fmaf(rc, hr, fmaf(-rs, hi, u));
        float hi2 = fmaf(rc, hi, rs * hr);
        hr = hr2; hi = hi2;
        outp[(size_t)i * 128 + k]      = hr;
        outp[(size_t)i * 128 + 64 + k] = hi;
    }
}

// ---------------- fused pipelined kernel ----------------
__global__ void __launch_bounds__(NTHREADS, 3)
fused_kernel(const float* __restrict__ x, const float* __restrict__ dtv_g,
             const float* __restrict__ amod, const float* __restrict__ omod,
             const float* __restrict__ tmod, float* __restrict__ out,
             const float* __restrict__ W, const float* __restrict__ bvec,
             const float* __restrict__ s_real, const float* __restrict__ s_imag,
             const float* __restrict__ tau_raw) {
    extern __shared__ float sm[];
    __shared__ int lastflag;
    const int bid = blockIdx.x;
    const int tid = threadIdx.x;

    if (bid == 0) {
        do_prep(sm, W, bvec, s_real, s_imag, tau_raw, tid);
    } else if (bid <= NGEMMB) {
        do_gemm(sm, x, W, bid - 1, tid);
    } else {
        do_scan(sm, dtv_g, amod, omod, tmod, out, bid - 1 - NGEMMB, tid);
    }

    // ---------- self-cleaning for graph replay ----------
    __syncthreads();
    if (tid == 0) {
        __threadfence();
        int c = atomicAdd(&g_done, 1);
        lastflag = (c == NBLK_TOTAL - 1) ? 1 : 0;
    }
    __syncthreads();
    if (lastflag) {
        for (int i = tid; i < NSCAN; i += NTHREADS) {
            g_flag[i] = 0;
            g_uflag[i] = 0;
        }
        if (tid == 0) {
            g_ready = 0;
            g_done = 0;
        }
    }
}

// ---------------- launch ----------------
extern "C" void kernel_launch(void* const* d_in, const int* in_sizes, int n_in,
                              void* d_out, int out_size) {
    const float* x      = (const float*)d_in[0];
    const float* dt     = (const float*)d_in[1];
    const float* amod   = (const float*)d_in[2];
    const float* omod   = (const float*)d_in[3];
    const float* tmod   = (const float*)d_in[4];
    const float* s_real = (const float*)d_in[5];
    const float* s_imag = (const float*)d_in[6];
    const float* tau_r  = (const float*)d_in[7];
    const float* W      = (const float*)d_in[8];
    const float* bvec   = (const float*)d_in[9];
    float* out = (float*)d_out;

    // 13312 floats = 53248 bytes (prep overlay == gemm tiles; scan uses 10368)
    static const size_t smem = 13312 * sizeof(float);

    cudaFuncSetAttribute(fused_kernel, cudaFuncAttributeMaxDynamicSharedMemorySize, (int)smem);

    fused_kernel<<<NBLK_TOTAL, NTHREADS, smem>>>(x, dt, amod, omod, tmod, out,
                                                 W, bvec, s_real, s_imag, tau_r);
}